// round 1
// baseline (speedup 1.0000x reference)
#include <cuda_runtime.h>
#include <cuda_bf16.h>

// BarlowTwinsLoss: loss = sum_d (1 - c_d)^2 where c_d is the per-column
// correlation of column-normalized e_q and tau, clipped to [-1+eps, 1-eps].
// Collapses to 5 per-column moments -> single streaming pass (HBM-bound).

#define D_FEAT 2048
#define ROW_BLOCKS 128          // row slices for stage-1 partials
#define TPB 256                 // threads per block
#define CPT 4                   // columns per thread (float4)
#define COLS_PER_BLOCK (TPB * CPT)   // 1024
#define GRID_X (D_FEAT / COLS_PER_BLOCK)  // 2
#define EPS 1e-9

// Deterministic scratch (no atomics): [5 moments][ROW_BLOCKS][D_FEAT] floats
__device__ float g_scratch[5 * ROW_BLOCKS * D_FEAT];   // 5.25 MB
__device__ double g_partials[8];

__global__ __launch_bounds__(TPB) void moments_kernel(
    const float* __restrict__ e, const float* __restrict__ t, int rows_per_block)
{
    const int col = (blockIdx.x * TPB + threadIdx.x) * CPT;
    const int rb  = blockIdx.y;
    const long long row0 = (long long)rb * rows_per_block;

    const float4* __restrict__ pe = (const float4*)(e + row0 * D_FEAT + col);
    const float4* __restrict__ pt = (const float4*)(t + row0 * D_FEAT + col);
    const int stride4 = D_FEAT / 4;   // float4 row stride

    float se[CPT], st[CPT], see[CPT], stt[CPT], set[CPT];
#pragma unroll
    for (int j = 0; j < CPT; j++) { se[j]=0.f; st[j]=0.f; see[j]=0.f; stt[j]=0.f; set[j]=0.f; }

#pragma unroll 4
    for (int r = 0; r < rows_per_block; r++) {
        float4 a = pe[(long long)r * stride4];
        float4 b = pt[(long long)r * stride4];
        float av[CPT] = {a.x, a.y, a.z, a.w};
        float bv[CPT] = {b.x, b.y, b.z, b.w};
#pragma unroll
        for (int j = 0; j < CPT; j++) {
            se[j]  += av[j];
            st[j]  += bv[j];
            see[j] = fmaf(av[j], av[j], see[j]);
            stt[j] = fmaf(bv[j], bv[j], stt[j]);
            set[j] = fmaf(av[j], bv[j], set[j]);
        }
    }

    // Write 5 float4s, coalesced: layout [k][rb][col]
    float* arrs[5] = {se, st, see, stt, set};
#pragma unroll
    for (int k = 0; k < 5; k++) {
        float4 v = make_float4(arrs[k][0], arrs[k][1], arrs[k][2], arrs[k][3]);
        *(float4*)&g_scratch[((long long)k * ROW_BLOCKS + rb) * D_FEAT + col] = v;
    }
}

__global__ __launch_bounds__(TPB) void reduce_kernel(int N)
{
    const int col = blockIdx.x * TPB + threadIdx.x;  // 8 blocks x 256 = 2048 cols

    double se = 0.0, st = 0.0, see = 0.0, stt = 0.0, set = 0.0;
#pragma unroll 4
    for (int rb = 0; rb < ROW_BLOCKS; rb++) {
        const long long base = (long long)rb * D_FEAT + col;
        se  += (double)g_scratch[(long long)0 * ROW_BLOCKS * D_FEAT + base];
        st  += (double)g_scratch[(long long)1 * ROW_BLOCKS * D_FEAT + base];
        see += (double)g_scratch[(long long)2 * ROW_BLOCKS * D_FEAT + base];
        stt += (double)g_scratch[(long long)3 * ROW_BLOCKS * D_FEAT + base];
        set += (double)g_scratch[(long long)4 * ROW_BLOCKS * D_FEAT + base];
    }

    const double dn = (double)N;
    double me = se / dn;
    double mt = st / dn;
    double var_e = (see - dn * me * me) / (dn - 1.0);
    double var_t = (stt - dn * mt * mt) / (dn - 1.0);
    double sde = fmax(sqrt(fmax(var_e, 0.0)), EPS);
    double sdt = fmax(sqrt(fmax(var_t, 0.0)), EPS);
    double cross = set - dn * me * mt;
    double c = cross / (sde * sdt) / (dn + EPS);
    c = fmin(fmax(c, -1.0 + EPS), 1.0 - EPS);
    double d1 = 1.0 - c;
    double term = d1 * d1;

    // block reduction (deterministic tree)
    __shared__ double sh[TPB];
    sh[threadIdx.x] = term;
    __syncthreads();
#pragma unroll
    for (int s = TPB / 2; s > 0; s >>= 1) {
        if (threadIdx.x < s) sh[threadIdx.x] += sh[threadIdx.x + s];
        __syncthreads();
    }
    if (threadIdx.x == 0) g_partials[blockIdx.x] = sh[0];
}

__global__ void final_kernel(float* __restrict__ out)
{
    double s = 0.0;
#pragma unroll
    for (int i = 0; i < 8; i++) s += g_partials[i];
    out[0] = (float)s;
}

extern "C" void kernel_launch(void* const* d_in, const int* in_sizes, int n_in,
                              void* d_out, int out_size)
{
    const float* e_q = (const float*)d_in[0];
    const float* tau = (const float*)d_in[1];
    float* out = (float*)d_out;

    const int N = in_sizes[0] / D_FEAT;           // 16384
    const int rows_per_block = N / ROW_BLOCKS;    // 128

    dim3 g1(GRID_X, ROW_BLOCKS);
    moments_kernel<<<g1, TPB>>>(e_q, tau, rows_per_block);
    reduce_kernel<<<D_FEAT / TPB, TPB>>>(N);
    final_kernel<<<1, 1>>>(out);
}

// round 2
// speedup vs baseline: 1.0602x; 1.0602x over previous
#include <cuda_runtime.h>
#include <cuda_bf16.h>

// BarlowTwinsLoss: loss = sum_d (1 - c_d)^2, c_d = per-column correlation of
// column-normalized e_q/tau (unbiased std), clipped. Collapses to 5 per-column
// moments (Se, St, See, Stt, Set) -> single HBM-bound streaming pass.

#define D_FEAT 2048
#define ROW_BLOCKS 256          // row slices for stage-1 partials
#define RPB 64                  // rows per row-block (16384/256)
#define TPB 256
#define CPT 4                   // columns per thread (float4)
#define COLS_PER_BLOCK (TPB * CPT)        // 1024
#define GRID_X (D_FEAT / COLS_PER_BLOCK)  // 2  -> grid = 512 blocks
#define EPS 1e-9

// Deterministic scratch (no atomics): [5][ROW_BLOCKS][D_FEAT] floats = 10.5 MB
__device__ float  g_scratch[5 * ROW_BLOCKS * D_FEAT];
__device__ double g_moments[5 * D_FEAT];

__global__ __launch_bounds__(TPB) void moments_kernel(
    const float* __restrict__ e, const float* __restrict__ t)
{
    const int col = (blockIdx.x * TPB + threadIdx.x) * CPT;
    const int rb  = blockIdx.y;
    const int row0 = rb * RPB;

    const float4* __restrict__ pe = (const float4*)(e + (size_t)row0 * D_FEAT + col);
    const float4* __restrict__ pt = (const float4*)(t + (size_t)row0 * D_FEAT + col);
    const int stride4 = D_FEAT / 4;

    float se[CPT], st[CPT], see[CPT], stt[CPT], set[CPT];
#pragma unroll
    for (int j = 0; j < CPT; j++) { se[j]=0.f; st[j]=0.f; see[j]=0.f; stt[j]=0.f; set[j]=0.f; }

#pragma unroll 8
    for (int r = 0; r < RPB; r++) {
        float4 a = pe[r * stride4];
        float4 b = pt[r * stride4];
        float av[CPT] = {a.x, a.y, a.z, a.w};
        float bv[CPT] = {b.x, b.y, b.z, b.w};
#pragma unroll
        for (int j = 0; j < CPT; j++) {
            se[j]  += av[j];
            st[j]  += bv[j];
            see[j] = fmaf(av[j], av[j], see[j]);
            stt[j] = fmaf(bv[j], bv[j], stt[j]);
            set[j] = fmaf(av[j], bv[j], set[j]);
        }
    }

    float* arrs[5] = {se, st, see, stt, set};
#pragma unroll
    for (int k = 0; k < 5; k++) {
        float4 v = make_float4(arrs[k][0], arrs[k][1], arrs[k][2], arrs[k][3]);
        *(float4*)&g_scratch[((size_t)k * ROW_BLOCKS + rb) * D_FEAT + col] = v;
    }
}

// 5*2048 = 10240 independent sums over ROW_BLOCKS partials: 40 blocks x 256.
__global__ __launch_bounds__(TPB) void reduce_moments_kernel()
{
    const int gid = blockIdx.x * TPB + threadIdx.x;   // 0..10239
    const int k   = gid / D_FEAT;
    const int col = gid % D_FEAT;

    const float* __restrict__ src = &g_scratch[(size_t)k * ROW_BLOCKS * D_FEAT + col];
    double s = 0.0;
#pragma unroll 8
    for (int rb = 0; rb < ROW_BLOCKS; rb++)
        s += (double)src[(size_t)rb * D_FEAT];
    g_moments[gid] = s;
}

// Single block: per-column loss term + deterministic tree reduction.
__global__ __launch_bounds__(TPB) void finalize_kernel(float* __restrict__ out, int N)
{
    const double dn = (double)N;
    double acc = 0.0;

    for (int col = threadIdx.x; col < D_FEAT; col += TPB) {
        double se  = g_moments[0 * D_FEAT + col];
        double st  = g_moments[1 * D_FEAT + col];
        double see = g_moments[2 * D_FEAT + col];
        double stt = g_moments[3 * D_FEAT + col];
        double set = g_moments[4 * D_FEAT + col];

        double me = se / dn;
        double mt = st / dn;
        double var_e = (see - dn * me * me) / (dn - 1.0);
        double var_t = (stt - dn * mt * mt) / (dn - 1.0);
        double sde = fmax(sqrt(fmax(var_e, 0.0)), EPS);
        double sdt = fmax(sqrt(fmax(var_t, 0.0)), EPS);
        double cross = set - dn * me * mt;
        double c = cross / (sde * sdt) / (dn + EPS);
        c = fmin(fmax(c, -1.0 + EPS), 1.0 - EPS);
        double d1 = 1.0 - c;
        acc += d1 * d1;
    }

    __shared__ double sh[TPB];
    sh[threadIdx.x] = acc;
    __syncthreads();
#pragma unroll
    for (int s = TPB / 2; s > 0; s >>= 1) {
        if (threadIdx.x < s) sh[threadIdx.x] += sh[threadIdx.x + s];
        __syncthreads();
    }
    if (threadIdx.x == 0) out[0] = (float)sh[0];
}

extern "C" void kernel_launch(void* const* d_in, const int* in_sizes, int n_in,
                              void* d_out, int out_size)
{
    const float* e_q = (const float*)d_in[0];
    const float* tau = (const float*)d_in[1];
    float* out = (float*)d_out;
    const int N = in_sizes[0] / D_FEAT;   // 16384

    dim3 g1(GRID_X, ROW_BLOCKS);
    moments_kernel<<<g1, TPB>>>(e_q, tau);
    reduce_moments_kernel<<<(5 * D_FEAT) / TPB, TPB>>>();
    finalize_kernel<<<1, TPB>>>(out, N);
}